// round 4
// baseline (speedup 1.0000x reference)
#include <cuda_runtime.h>
#include <math.h>

#define BB 4
#define CC 8
#define HH 192
#define WW 256
#define NP (HH*WW)
#define GEOM_Wf 0.01f
#define NB 444                 // 148 SMs * 3 resident blocks
#define NCHUNK (BB*(NP/256))   // 768 chunks of 256 pixels

// ---------------- scratch (static device globals; no allocation) -------------
__device__ float4 g_ch[BB*CC*NP];   // (I0, dIx, dIy, 0) per (b,c,pix)
__device__ float4 g_vn[BB*NP*2];    // (V0x,V0y,V0z,N0x), (N0y,N0z,0,0)
__device__ float4 g_v1[BB*NP];      // (V1x,V1y,V1z,0)
__device__ float  g_pose[BB*16];
__device__ double g_acc[BB*27];
__device__ unsigned int g_bar_count = 0;
__device__ unsigned int g_bar_gen   = 0;

// ---------------- grid barrier (all NB blocks resident) -----------------------
__device__ __forceinline__ void grid_barrier(bool wait) {
    __syncthreads();
    if (threadIdx.x == 0) {
        __threadfence();
        unsigned int gen = atomicAdd(&g_bar_gen, 0u);
        unsigned int t   = atomicAdd(&g_bar_count, 1u);
        if (t == NB - 1) {
            g_bar_count = 0;
            __threadfence();
            atomicAdd(&g_bar_gen, 1u);
        } else if (wait) {
            while (atomicAdd(&g_bar_gen, 0u) == gen) __nanosleep(64);
        }
        __threadfence();
    }
    __syncthreads();
}

// ---------------- helpers ------------------------------------------------------
__device__ __forceinline__ void bilin_setup(float uu, float vv, int* idx, float* wt) {
    float u0 = floorf(uu), v0 = floorf(vv);
    float du = uu - u0, dv = vv - v0;
    float us[2] = {u0, u0 + 1.0f};
    float vs[2] = {v0, v0 + 1.0f};
    float wu[2] = {1.0f - du, du};
    float wv[2] = {1.0f - dv, dv};
    #pragma unroll
    for (int j = 0; j < 2; j++)
        #pragma unroll
        for (int i2 = 0; i2 < 2; i2++) {
            float uf = us[i2], vf = vs[j];
            bool in = (uf >= 0.0f) && (uf <= (float)(WW-1)) &&
                      (vf >= 0.0f) && (vf <= (float)(HH-1));
            int ui = (int)fminf(fmaxf(uf, 0.0f), (float)(WW-1));
            int vi = (int)fminf(fmaxf(vf, 0.0f), (float)(HH-1));
            idx[j*2+i2] = vi*WW + ui;
            wt[j*2+i2]  = wu[i2]*wv[j] * (in ? 1.0f : 0.0f);
        }
}

// ---------------- per-batch GN solve + se3_exp + pose compose -----------------
__device__ __noinline__ void solve_update(int b, float* out) {
    double M[6][7];
    {
        int id = 0;
        double Hm[6][6];
        for (int i = 0; i < 6; i++)
            for (int j = i; j < 6; j++) {
                double vv = g_acc[b*27 + id++];
                Hm[i][j] = vv; Hm[j][i] = vv;
            }
        for (int i = 0; i < 6; i++) Hm[i][i] += 1e-6;
        for (int i = 0; i < 6; i++) {
            for (int j = 0; j < 6; j++) M[i][j] = Hm[i][j];
            M[i][6] = g_acc[b*27 + 21 + i];
        }
    }
    for (int col = 0; col < 6; col++) {
        int piv = col; double mx = fabs(M[col][col]);
        for (int r = col+1; r < 6; r++)
            if (fabs(M[r][col]) > mx) { mx = fabs(M[r][col]); piv = r; }
        if (piv != col)
            for (int j = col; j < 7; j++) { double tmp = M[col][j]; M[col][j] = M[piv][j]; M[piv][j] = tmp; }
        double d = M[col][col];
        for (int r = col+1; r < 6; r++) {
            double f = M[r][col] / d;
            for (int j = col; j < 7; j++) M[r][j] -= f * M[col][j];
        }
    }
    double xi[6];
    for (int i = 5; i >= 0; i--) {
        double s = M[i][6];
        for (int j = i+1; j < 6; j++) s -= M[i][j]*xi[j];
        xi[i] = s / M[i][i];
    }

    double W0 = xi[0], W1 = xi[1], W2 = xi[2];
    double V0v = xi[3], V1vd = xi[4], V2v = xi[5];
    double th2 = W0*W0 + W1*W1 + W2*W2;
    bool small = th2 < 1e-8;
    double th2s = small ? 1.0 : th2;
    double th = sqrt(th2s);
    double Aa = small ? (1.0 - th2/6.0)       : (sin(th)/th);
    double Bc = small ? (0.5 - th2/24.0)      : ((1.0 - cos(th))/th2s);
    double Cc = small ? (1.0/6.0 - th2/120.0) : ((th - sin(th))/(th2s*th));
    double K[3][3] = {{0,-W2,W1},{W2,0,-W0},{-W1,W0,0}};
    double K2[3][3];
    for (int i = 0; i < 3; i++)
        for (int j = 0; j < 3; j++) {
            double s = 0.0;
            for (int k = 0; k < 3; k++) s += K[i][k]*K[k][j];
            K2[i][j] = s;
        }
    double Rm[3][3], Vm[3][3];
    for (int i = 0; i < 3; i++)
        for (int j = 0; j < 3; j++) {
            double eye = (i == j) ? 1.0 : 0.0;
            Rm[i][j] = eye + Aa*K[i][j] + Bc*K2[i][j];
            Vm[i][j] = eye + Bc*K[i][j] + Cc*K2[i][j];
        }
    double tt[3];
    tt[0] = Vm[0][0]*V0v + Vm[0][1]*V1vd + Vm[0][2]*V2v;
    tt[1] = Vm[1][0]*V0v + Vm[1][1]*V1vd + Vm[1][2]*V2v;
    tt[2] = Vm[2][0]*V0v + Vm[2][1]*V1vd + Vm[2][2]*V2v;

    double T[4][4] = {{Rm[0][0],Rm[0][1],Rm[0][2],tt[0]},
                      {Rm[1][0],Rm[1][1],Rm[1][2],tt[1]},
                      {Rm[2][0],Rm[2][1],Rm[2][2],tt[2]},
                      {0,0,0,1}};
    double Pold[4][4];
    for (int i = 0; i < 4; i++)
        for (int j = 0; j < 4; j++) Pold[i][j] = (double)g_pose[b*16 + i*4 + j];
    for (int i = 0; i < 4; i++)
        for (int j = 0; j < 4; j++) {
            double s = 0.0;
            for (int k = 0; k < 4; k++) s += T[i][k]*Pold[k][j];
            float fv = (float)s;
            g_pose[b*16 + i*4 + j] = fv;
            if (out) out[b*16 + i*4 + j] = fv;
        }
    for (int k = 0; k < 27; k++) g_acc[b*27 + k] = 0.0;
}

// ---------------- the whole pipeline as one persistent kernel -----------------
__global__ void __launch_bounds__(256, 3)
fusedK(const float* __restrict__ pose, const float* __restrict__ intr,
       const float* __restrict__ I0,  const float* __restrict__ I1,
       const float* __restrict__ depth0, const float* __restrict__ depth1,
       float* __restrict__ out) {
    const int tid = threadIdx.x;

    // ================= phase 0: prep =================
    if (blockIdx.x == 0) {
        if (tid < BB*16) g_pose[tid] = pose[tid];
        if (tid < BB*27) g_acc[tid]  = 0.0;
    }
    for (int i = blockIdx.x*256 + tid; i < BB*NP; i += NB*256) {
        int b = i / NP, pix = i - b*NP;
        int h = pix / WW, w = pix - h*WW;
        int wm = max(w-1, 0), wp = min(w+1, WW-1);
        int hm = max(h-1, 0), hp = min(h+1, HH-1);

        float fx = intr[b*4+0], fy = intr[b*4+1], cx = intr[b*4+2], cy = intr[b*4+3];
        const float* D0 = depth0 + (size_t)b*NP;

        float px = ((float)w - cx) / fx;
        float py = ((float)h - cy) / fy;
        float d0 = D0[pix];
        float d1 = depth1[i];
        g_v1[i] = make_float4(px*d1, py*d1, d1, 0.f);

        float dxp = D0[h*WW+wp], dxm = D0[h*WW+wm];
        float dyp = D0[hp*WW+w], dym = D0[hm*WW+w];
        float pxp = ((float)wp - cx)/fx, pxm = ((float)wm - cx)/fx;
        float pyp = ((float)hp - cy)/fy, pym = ((float)hm - cy)/fy;
        float dx0 = (pxp*dxp - pxm*dxm) * 0.5f;
        float dx1 = (py*dxp  - py*dxm ) * 0.5f;
        float dx2 = (dxp     - dxm    ) * 0.5f;
        float dy0 = (px*dyp  - px*dym ) * 0.5f;
        float dy1 = (pyp*dyp - pym*dym) * 0.5f;
        float dy2 = (dyp     - dym    ) * 0.5f;
        float n0 = dx1*dy2 - dx2*dy1;
        float n1 = dx2*dy0 - dx0*dy2;
        float n2 = dx0*dy1 - dx1*dy0;
        float inv = 1.0f / sqrtf(n0*n0 + n1*n1 + n2*n2 + 1e-12f);
        g_vn[(size_t)i*2+0] = make_float4(px*d0, py*d0, d0, n0*inv);
        g_vn[(size_t)i*2+1] = make_float4(n1*inv, n2*inv, 0.f, 0.f);

        #pragma unroll
        for (int c = 0; c < CC; c++) {
            const float* Ic = I0 + (size_t)(b*CC+c)*NP;
            float gx = (Ic[h*WW+wp] - Ic[h*WW+wm]) * 0.5f;
            float gy = (Ic[hp*WW+w] - Ic[hm*WW+w]) * 0.5f;
            g_ch[(size_t)(b*CC+c)*NP + pix] = make_float4(Ic[pix], gx, gy, 0.f);
        }
    }
    grid_barrier(true);

    // ================= phases 1..3: GN iterations =================
    __shared__ float sred[8][27];
    for (int it = 0; it < 3; it++) {
        for (int cidx = blockIdx.x; cidx < NCHUNK; cidx += NB) {
            const int b   = cidx / (NP/256);
            const int pix = (cidx % (NP/256)) * 256 + tid;
            const size_t bNP = (size_t)b*NP;

            const float* P = g_pose + b*16;
            float R00=P[0], R01=P[1], R02=P[2],  t0=P[3];
            float R10=P[4], R11=P[5], R12=P[6],  t1=P[7];
            float R20=P[8], R21=P[9], R22=P[10], t2=P[11];
            float fx = intr[b*4+0], fy = intr[b*4+1], cx = intr[b*4+2], cy = intr[b*4+3];

            float4 V1v4 = g_v1[bNP + pix];
            float X1 = V1v4.x, Y1 = V1v4.y, Z1 = V1v4.z;
            float d1v = Z1;

            float x = R00*X1 + R01*Y1 + R02*Z1 + t0;
            float y = R10*X1 + R11*Y1 + R12*Z1 + t1;
            float z = R20*X1 + R21*Y1 + R22*Z1 + t2;

            bool  valid0 = z > 1e-8f;
            float zs = (fabsf(z) > 1e-8f) ? z : 1e-8f;
            float u = fx*x/zs + cx;
            float v = fy*y/zs + cy;
            bool inb = (u > 0.0f) && (u < (float)(WW-1)) && (v > 0.0f) && (v < (float)(HH-1));
            float d0 = depth0[bNP + pix];
            bool valid = inb && valid0 && (d0 > 0.0f) && (d1v > 0.0f);

            float Sxx=0.f, Sxy=0.f, Syy=0.f, Sxr=0.f, Syr=0.f;
            float Jg0=0.f, Jg1=0.f, Jg2=0.f, Jg3=0.f, Jg4=0.f, Jg5=0.f;
            float wgr=0.f, wg=0.f;

            if (valid) {
                float gxg = fminf(fmaxf((u/(float)(WW-1) - 0.5f)*2.0f, -2.0f), 2.0f);
                float gyg = fminf(fmaxf((v/(float)(HH-1) - 0.5f)*2.0f, -2.0f), 2.0f);
                float up = (gxg + 1.0f)*0.5f*(float)(WW-1);
                float vp = (gyg + 1.0f)*0.5f*(float)(HH-1);
                int   idxp[4]; float wp_[4];
                bilin_setup(up, vp, idxp, wp_);

                const float4* pc = g_ch + bNP*CC;
                #pragma unroll
                for (int c = 0; c < CC; c++) {
                    const float4* pl = pc + (size_t)c*NP;
                    float4 A = pl[idxp[0]], Bq = pl[idxp[1]],
                           Cq = pl[idxp[2]], Dq = pl[idxp[3]];
                    float i0w = wp_[0]*A.x + wp_[1]*Bq.x + wp_[2]*Cq.x + wp_[3]*Dq.x;
                    float gxv = wp_[0]*A.y + wp_[1]*Bq.y + wp_[2]*Cq.y + wp_[3]*Dq.y;
                    float gyv = wp_[0]*A.z + wp_[1]*Bq.z + wp_[2]*Cq.z + wp_[3]*Dq.z;
                    float r = I1[(size_t)(b*CC+c)*NP + pix] - i0w;
                    float ar = fabsf(r);
                    float wt = (ar <= 0.5f) ? 1.0f : 0.5f / fmaxf(ar, 1e-12f);
                    float wgx = wt*gxv, wgy = wt*gyv;
                    Sxx += wgx*gxv; Sxy += wgx*gyv; Syy += wgy*gyv;
                    Sxr += wgx*r;   Syr += wgy*r;
                }

                // ---- geometric (ICP point-to-plane) row ----
                float ui = x/zs*fx + cx;
                float vi = y/zs*fy + cy;
                int   idxg[4]; float wg_[4];
                bilin_setup(ui, vi, idxg, wg_);

                float rv0=0.f, rv1=0.f, rv2=0.f, rn0=0.f, rn1=0.f, rn2=0.f;
                #pragma unroll
                for (int k = 0; k < 4; k++) {
                    const float4* vp2 = g_vn + (bNP + idxg[k])*2;
                    float4 A = vp2[0], Bv = vp2[1];
                    float wk = wg_[k];
                    rv0 += wk*A.x; rv1 += wk*A.y; rv2 += wk*A.z;
                    rn0 += wk*A.w; rn1 += wk*Bv.x; rn2 += wk*Bv.y;
                }
                float dx_ = x - rv0, dy_ = y - rv1, dz_ = z - rv2;
                float dn  = sqrtf(dx_*dx_ + dy_*dy_ + dz_*dz_ + 1e-12f);
                bool  occ = dn > 0.1f;

                float N0c = rn0*R00 + rn1*R10 + rn2*R20;
                float N1c = rn0*R01 + rn1*R11 + rn2*R21;
                float N2c = rn0*R02 + rn1*R12 + rn2*R22;
                float Jr0 = N1c*Z1 - N2c*Y1;
                float Jr1 = N2c*X1 - N0c*Z1;
                float Jr2 = N0c*Y1 - N1c*X1;

                float sdxy = d1v / 525.0f * 5.5f;
                float sdz  = d1v * d1v * 0.4f / (525.0f * 1.2f);
                float cov  = (N0c*N0c + N1c*N1c)*sdxy*sdxy + N2c*N2c*sdz*sdz;
                float sigma = sqrtf(cov + 1e-8f);
                float inv   = 1.0f / (sigma + 1e-8f);

                float res = (rn0*dx_ + rn1*dy_ + rn2*dz_) * inv;
                if (occ) res = 1e-6f;
                Jg0 = GEOM_Wf*(-Jr0*inv); Jg1 = GEOM_Wf*(-Jr1*inv); Jg2 = GEOM_Wf*(-Jr2*inv);
                Jg3 = GEOM_Wf*( N0c*inv); Jg4 = GEOM_Wf*( N1c*inv); Jg5 = GEOM_Wf*( N2c*inv);
                float rg = -GEOM_Wf*res;
                float arg = fabsf(rg);
                wg  = (arg <= 0.5f) ? 1.0f : 0.5f / fmaxf(arg, 1e-12f);
                wgr = wg * rg;
            }

            float a  =  fx/zs;
            float bq = -fx*x/(zs*zs);
            float c2 =  fy/zs;
            float d2 = -fy*y/(zs*zs);
            float Jw0[6] = { bq*y,       a*z - bq*x, -a*y, a,   0.f, bq };
            float Jw1[6] = { -c2*z+d2*y, -d2*x,       c2*x, 0.f, c2,  d2 };

            float acc[27];
            {
                float Jga[6] = {Jg0, Jg1, Jg2, Jg3, Jg4, Jg5};
                float Pe[6], Qe[6];
                #pragma unroll
                for (int i2 = 0; i2 < 6; i2++) {
                    Pe[i2] = Sxx*Jw0[i2] + Sxy*Jw1[i2];
                    Qe[i2] = Sxy*Jw0[i2] + Syy*Jw1[i2];
                }
                int id = 0;
                #pragma unroll
                for (int i2 = 0; i2 < 6; i2++) {
                    float wJg = wg * Jga[i2];
                    #pragma unroll
                    for (int j2 = i2; j2 < 6; j2++)
                        acc[id++] = Pe[i2]*Jw0[j2] + Qe[i2]*Jw1[j2] + wJg*Jga[j2];
                    acc[21+i2] = Sxr*Jw0[i2] + Syr*Jw1[i2] + wgr*Jga[i2];
                }
            }

            #pragma unroll
            for (int off = 16; off > 0; off >>= 1)
                #pragma unroll
                for (int k = 0; k < 27; k++)
                    acc[k] += __shfl_down_sync(0xffffffffu, acc[k], off);

            int lane = tid & 31, wid = tid >> 5;
            __syncthreads();            // protect sred reuse across chunks
            if (lane == 0)
                #pragma unroll
                for (int k = 0; k < 27; k++) sred[wid][k] = acc[k];
            __syncthreads();
            if (tid < 27) {
                float sv = 0.f;
                #pragma unroll
                for (int w2 = 0; w2 < 8; w2++) sv += sred[w2][tid];
                atomicAdd(&g_acc[b*27 + tid], (double)sv);
            }
        }

        // pre-solve barrier; on the last iteration non-solver blocks just arrive+exit
        bool last = (it == 2);
        grid_barrier(!last || blockIdx.x == 0);
        if (blockIdx.x == 0 && tid < BB)
            solve_update(tid, last ? out : nullptr);
        if (!last) grid_barrier(true);   // publish new pose
        else if (blockIdx.x != 0) return;
    }
}

// ---------------- launch --------------------------------------------------------
extern "C" void kernel_launch(void* const* d_in, const int* in_sizes, int n_in,
                              void* d_out, int out_size) {
    const float* pose   = (const float*)d_in[0];
    const float* I0     = (const float*)d_in[1];
    const float* I1     = (const float*)d_in[2];
    const float* intr   = (const float*)d_in[5];
    const float* depth0 = (const float*)d_in[6];
    const float* depth1 = (const float*)d_in[7];

    fusedK<<<NB, 256>>>(pose, intr, I0, I1, depth0, depth1, (float*)d_out);
}

// round 7
// speedup vs baseline: 1.0461x; 1.0461x over previous
#include <cuda_runtime.h>
#include <math.h>

#define BB 4
#define CC 8
#define HH 192
#define WW 256
#define NP (HH*WW)
#define GEOM_Wf 0.01f
#define NBLK (BB*(NP/256))      // 768 blocks, one 256-pixel chunk each

// ---------------- scratch (static device globals; no allocation) -------------
__device__ float4 g_ch[BB*CC*NP];   // (I0, dIx, dIy, 0) per (b,c,pix)
__device__ float4 g_vn[BB*NP*2];    // (V0x,V0y,V0z,N0x), (N0y,N0z,0,0)
__device__ float4 g_v1[BB*NP];      // (V1x,V1y,V1z,0)
__device__ float  g_pose[BB*16];
__device__ double g_acc[BB*27];
__device__ unsigned int g_done = 0;

// ---------------- fused prep: vertices, normals, gradients, init --------------
__global__ void __launch_bounds__(256)
prepK(const float* __restrict__ pose, const float* __restrict__ intr,
      const float* __restrict__ I0,
      const float* __restrict__ depth0, const float* __restrict__ depth1) {
    int i = blockIdx.x*256 + threadIdx.x;
    if (blockIdx.x == 0) {
        int t = threadIdx.x;
        if (t < BB*16) g_pose[t] = pose[t];
        if (t < BB*27) g_acc[t]  = 0.0;
        if (t == 0)    g_done    = 0u;
    }
    if (i >= BB*NP) return;
    int b = i / NP, pix = i - b*NP;
    int h = pix / WW, w = pix - h*WW;
    int wm = max(w-1, 0), wp = min(w+1, WW-1);
    int hm = max(h-1, 0), hp = min(h+1, HH-1);

    float fx = intr[b*4+0], fy = intr[b*4+1], cx = intr[b*4+2], cy = intr[b*4+3];
    const float* D0 = depth0 + (size_t)b*NP;

    float px = ((float)w - cx) / fx;
    float py = ((float)h - cy) / fy;
    float d0 = D0[pix];
    float d1 = depth1[i];
    g_v1[i] = make_float4(px*d1, py*d1, d1, 0.f);

    // V0 normal via analytic neighbor recompute (matches edge-pad central diff)
    float dxp = D0[h*WW+wp], dxm = D0[h*WW+wm];
    float dyp = D0[hp*WW+w], dym = D0[hm*WW+w];
    float pxp = ((float)wp - cx)/fx, pxm = ((float)wm - cx)/fx;
    float pyp = ((float)hp - cy)/fy, pym = ((float)hm - cy)/fy;
    float dx0 = (pxp*dxp - pxm*dxm) * 0.5f;
    float dx1 = (py*dxp  - py*dxm ) * 0.5f;
    float dx2 = (dxp     - dxm    ) * 0.5f;
    float dy0 = (px*dyp  - px*dym ) * 0.5f;
    float dy1 = (pyp*dyp - pym*dym) * 0.5f;
    float dy2 = (dyp     - dym    ) * 0.5f;
    float n0 = dx1*dy2 - dx2*dy1;
    float n1 = dx2*dy0 - dx0*dy2;
    float n2 = dx0*dy1 - dx1*dy0;
    float inv = 1.0f / sqrtf(n0*n0 + n1*n1 + n2*n2 + 1e-12f);
    g_vn[(size_t)i*2+0] = make_float4(px*d0, py*d0, d0, n0*inv);
    g_vn[(size_t)i*2+1] = make_float4(n1*inv, n2*inv, 0.f, 0.f);

    #pragma unroll
    for (int c = 0; c < CC; c++) {
        const float* Ic = I0 + (size_t)(b*CC+c)*NP;
        float gx = (Ic[h*WW+wp] - Ic[h*WW+wm]) * 0.5f;
        float gy = (Ic[hp*WW+w] - Ic[hm*WW+w]) * 0.5f;
        g_ch[(size_t)(b*CC+c)*NP + pix] = make_float4(Ic[pix], gx, gy, 0.f);
    }
}

// ---------------- helpers ------------------------------------------------------
__device__ __forceinline__ void bilin_setup(float uu, float vv, int* idx, float* wt) {
    float u0 = floorf(uu), v0 = floorf(vv);
    float du = uu - u0, dv = vv - v0;
    float us[2] = {u0, u0 + 1.0f};
    float vs[2] = {v0, v0 + 1.0f};
    float wu[2] = {1.0f - du, du};
    float wv[2] = {1.0f - dv, dv};
    #pragma unroll
    for (int j = 0; j < 2; j++)
        #pragma unroll
        for (int i2 = 0; i2 < 2; i2++) {
            float uf = us[i2], vf = vs[j];
            bool in = (uf >= 0.0f) && (uf <= (float)(WW-1)) &&
                      (vf >= 0.0f) && (vf <= (float)(HH-1));
            int ui = (int)fminf(fmaxf(uf, 0.0f), (float)(WW-1));
            int vi = (int)fminf(fmaxf(vf, 0.0f), (float)(HH-1));
            idx[j*2+i2] = vi*WW + ui;
            wt[j*2+i2]  = wu[i2]*wv[j] * (in ? 1.0f : 0.0f);
        }
}

// ---------------- per-batch GN solve + se3_exp + pose compose -----------------
__device__ __noinline__ void solve_update(int b, float* out) {
    double M[6][7];
    {
        int id = 0;
        double Hm[6][6];
        for (int i = 0; i < 6; i++)
            for (int j = i; j < 6; j++) {
                double vv = atomicAdd(&g_acc[b*27 + id], 0.0);   // L2-coherent read
                id++;
                Hm[i][j] = vv; Hm[j][i] = vv;
            }
        for (int i = 0; i < 6; i++) Hm[i][i] += 1e-6;
        for (int i = 0; i < 6; i++) {
            for (int j = 0; j < 6; j++) M[i][j] = Hm[i][j];
            M[i][6] = atomicAdd(&g_acc[b*27 + 21 + i], 0.0);
        }
    }
    for (int col = 0; col < 6; col++) {
        int piv = col; double mx = fabs(M[col][col]);
        for (int r = col+1; r < 6; r++)
            if (fabs(M[r][col]) > mx) { mx = fabs(M[r][col]); piv = r; }
        if (piv != col)
            for (int j = col; j < 7; j++) { double tmp = M[col][j]; M[col][j] = M[piv][j]; M[piv][j] = tmp; }
        double d = M[col][col];
        for (int r = col+1; r < 6; r++) {
            double f = M[r][col] / d;
            for (int j = col; j < 7; j++) M[r][j] -= f * M[col][j];
        }
    }
    double xi[6];
    for (int i = 5; i >= 0; i--) {
        double s = M[i][6];
        for (int j = i+1; j < 6; j++) s -= M[i][j]*xi[j];
        xi[i] = s / M[i][i];
    }

    double W0 = xi[0], W1 = xi[1], W2 = xi[2];
    double V0v = xi[3], V1vd = xi[4], V2v = xi[5];
    double th2 = W0*W0 + W1*W1 + W2*W2;
    bool small = th2 < 1e-8;
    double th2s = small ? 1.0 : th2;
    double th = sqrt(th2s);
    double Aa = small ? (1.0 - th2/6.0)       : (sin(th)/th);
    double Bc = small ? (0.5 - th2/24.0)      : ((1.0 - cos(th))/th2s);
    double Cc = small ? (1.0/6.0 - th2/120.0) : ((th - sin(th))/(th2s*th));
    double K[3][3] = {{0,-W2,W1},{W2,0,-W0},{-W1,W0,0}};
    double K2[3][3];
    for (int i = 0; i < 3; i++)
        for (int j = 0; j < 3; j++) {
            double s = 0.0;
            for (int k = 0; k < 3; k++) s += K[i][k]*K[k][j];
            K2[i][j] = s;
        }
    double Rm[3][3], Vm[3][3];
    for (int i = 0; i < 3; i++)
        for (int j = 0; j < 3; j++) {
            double eye = (i == j) ? 1.0 : 0.0;
            Rm[i][j] = eye + Aa*K[i][j] + Bc*K2[i][j];
            Vm[i][j] = eye + Bc*K[i][j] + Cc*K2[i][j];
        }
    double tt[3];
    tt[0] = Vm[0][0]*V0v + Vm[0][1]*V1vd + Vm[0][2]*V2v;
    tt[1] = Vm[1][0]*V0v + Vm[1][1]*V1vd + Vm[1][2]*V2v;
    tt[2] = Vm[2][0]*V0v + Vm[2][1]*V1vd + Vm[2][2]*V2v;

    double T[4][4] = {{Rm[0][0],Rm[0][1],Rm[0][2],tt[0]},
                      {Rm[1][0],Rm[1][1],Rm[1][2],tt[1]},
                      {Rm[2][0],Rm[2][1],Rm[2][2],tt[2]},
                      {0,0,0,1}};
    double Pold[4][4];
    for (int i = 0; i < 4; i++)
        for (int j = 0; j < 4; j++) Pold[i][j] = (double)g_pose[b*16 + i*4 + j];
    for (int i = 0; i < 4; i++)
        for (int j = 0; j < 4; j++) {
            double s = 0.0;
            for (int k = 0; k < 4; k++) s += T[i][k]*Pold[k][j];
            float fv = (float)s;
            g_pose[b*16 + i*4 + j] = fv;
            if (out) out[b*16 + i*4 + j] = fv;
        }
    for (int k = 0; k < 27; k++) g_acc[b*27 + k] = 0.0;
}

// ---------------- main per-iteration kernel (solve fused in last block) --------
__global__ void __launch_bounds__(256, 3)
iterK(const float* __restrict__ I1, const float* __restrict__ intr,
      const float* __restrict__ depth0, float* __restrict__ out) {
    const int BPB = NP / 256;
    const int b   = blockIdx.x / BPB;
    const int pix = (blockIdx.x % BPB) * 256 + threadIdx.x;
    const size_t bNP = (size_t)b*NP;

    const float* P = g_pose + b*16;
    float R00=P[0], R01=P[1], R02=P[2],  t0=P[3];
    float R10=P[4], R11=P[5], R12=P[6],  t1=P[7];
    float R20=P[8], R21=P[9], R22=P[10], t2=P[11];
    float fx = intr[b*4+0], fy = intr[b*4+1], cx = intr[b*4+2], cy = intr[b*4+3];

    float4 V1v4 = g_v1[bNP + pix];
    float X1 = V1v4.x, Y1 = V1v4.y, Z1 = V1v4.z;
    float d1v = Z1;

    float x = R00*X1 + R01*Y1 + R02*Z1 + t0;
    float y = R10*X1 + R11*Y1 + R12*Z1 + t1;
    float z = R20*X1 + R21*Y1 + R22*Z1 + t2;

    bool  valid0 = z > 1e-8f;
    float zs = (fabsf(z) > 1e-8f) ? z : 1e-8f;
    float u = fx*x/zs + cx;
    float v = fy*y/zs + cy;
    bool inb = (u > 0.0f) && (u < (float)(WW-1)) && (v > 0.0f) && (v < (float)(HH-1));
    float d0 = depth0[bNP + pix];
    bool valid = inb && valid0 && (d0 > 0.0f) && (d1v > 0.0f);

    float Sxx=0.f, Sxy=0.f, Syy=0.f, Sxr=0.f, Syr=0.f;
    float Jg0=0.f, Jg1=0.f, Jg2=0.f, Jg3=0.f, Jg4=0.f, Jg5=0.f;
    float wgr=0.f, wg=0.f;

    if (valid) {
        float gxg = fminf(fmaxf((u/(float)(WW-1) - 0.5f)*2.0f, -2.0f), 2.0f);
        float gyg = fminf(fmaxf((v/(float)(HH-1) - 0.5f)*2.0f, -2.0f), 2.0f);
        float up = (gxg + 1.0f)*0.5f*(float)(WW-1);
        float vp = (gyg + 1.0f)*0.5f*(float)(HH-1);
        int   idxp[4]; float wp_[4];
        bilin_setup(up, vp, idxp, wp_);

        const float4* pc = g_ch + bNP*CC;
        #pragma unroll
        for (int c = 0; c < CC; c++) {
            const float4* pl = pc + (size_t)c*NP;
            float4 A = pl[idxp[0]], Bq = pl[idxp[1]],
                   Cq = pl[idxp[2]], Dq = pl[idxp[3]];
            float i0w = wp_[0]*A.x + wp_[1]*Bq.x + wp_[2]*Cq.x + wp_[3]*Dq.x;
            float gxv = wp_[0]*A.y + wp_[1]*Bq.y + wp_[2]*Cq.y + wp_[3]*Dq.y;
            float gyv = wp_[0]*A.z + wp_[1]*Bq.z + wp_[2]*Cq.z + wp_[3]*Dq.z;
            float r = I1[(size_t)(b*CC+c)*NP + pix] - i0w;
            float ar = fabsf(r);
            float wt = (ar <= 0.5f) ? 1.0f : 0.5f / fmaxf(ar, 1e-12f);
            float wgx = wt*gxv, wgy = wt*gyv;
            Sxx += wgx*gxv; Sxy += wgx*gyv; Syy += wgy*gyv;
            Sxr += wgx*r;   Syr += wgy*r;
        }

        // ---- geometric (ICP point-to-plane) row ----
        float ui = x/zs*fx + cx;
        float vi = y/zs*fy + cy;
        int   idxg[4]; float wg_[4];
        bilin_setup(ui, vi, idxg, wg_);

        float rv0=0.f, rv1=0.f, rv2=0.f, rn0=0.f, rn1=0.f, rn2=0.f;
        #pragma unroll
        for (int k = 0; k < 4; k++) {
            const float4* vp2 = g_vn + (bNP + idxg[k])*2;
            float4 A = vp2[0], Bv = vp2[1];
            float wk = wg_[k];
            rv0 += wk*A.x; rv1 += wk*A.y; rv2 += wk*A.z;
            rn0 += wk*A.w; rn1 += wk*Bv.x; rn2 += wk*Bv.y;
        }
        float dx_ = x - rv0, dy_ = y - rv1, dz_ = z - rv2;
        float dn  = sqrtf(dx_*dx_ + dy_*dy_ + dz_*dz_ + 1e-12f);
        bool  occ = dn > 0.1f;

        float N0c = rn0*R00 + rn1*R10 + rn2*R20;
        float N1c = rn0*R01 + rn1*R11 + rn2*R21;
        float N2c = rn0*R02 + rn1*R12 + rn2*R22;
        float Jr0 = N1c*Z1 - N2c*Y1;
        float Jr1 = N2c*X1 - N0c*Z1;
        float Jr2 = N0c*Y1 - N1c*X1;

        float sdxy = d1v / 525.0f * 5.5f;
        float sdz  = d1v * d1v * 0.4f / (525.0f * 1.2f);
        float cov  = (N0c*N0c + N1c*N1c)*sdxy*sdxy + N2c*N2c*sdz*sdz;
        float sigma = sqrtf(cov + 1e-8f);
        float inv   = 1.0f / (sigma + 1e-8f);

        float res = (rn0*dx_ + rn1*dy_ + rn2*dz_) * inv;
        if (occ) res = 1e-6f;
        Jg0 = GEOM_Wf*(-Jr0*inv); Jg1 = GEOM_Wf*(-Jr1*inv); Jg2 = GEOM_Wf*(-Jr2*inv);
        Jg3 = GEOM_Wf*( N0c*inv); Jg4 = GEOM_Wf*( N1c*inv); Jg5 = GEOM_Wf*( N2c*inv);
        float rg = -GEOM_Wf*res;
        float arg = fabsf(rg);
        wg  = (arg <= 0.5f) ? 1.0f : 0.5f / fmaxf(arg, 1e-12f);
        wgr = wg * rg;
    }

    float a  =  fx/zs;
    float bq = -fx*x/(zs*zs);
    float c2 =  fy/zs;
    float d2 = -fy*y/(zs*zs);
    float Jw0[6] = { bq*y,       a*z - bq*x, -a*y, a,   0.f, bq };
    float Jw1[6] = { -c2*z+d2*y, -d2*x,       c2*x, 0.f, c2,  d2 };

    float acc[27];
    {
        float Jga[6] = {Jg0, Jg1, Jg2, Jg3, Jg4, Jg5};
        float Pe[6], Qe[6];
        #pragma unroll
        for (int i2 = 0; i2 < 6; i2++) {
            Pe[i2] = Sxx*Jw0[i2] + Sxy*Jw1[i2];
            Qe[i2] = Sxy*Jw0[i2] + Syy*Jw1[i2];
        }
        int id = 0;
        #pragma unroll
        for (int i2 = 0; i2 < 6; i2++) {
            float wJg = wg * Jga[i2];
            #pragma unroll
            for (int j2 = i2; j2 < 6; j2++)
                acc[id++] = Pe[i2]*Jw0[j2] + Qe[i2]*Jw1[j2] + wJg*Jga[j2];
            acc[21+i2] = Sxr*Jw0[i2] + Syr*Jw1[i2] + wgr*Jga[i2];
        }
    }

    // ---- block reduction: warp shuffle -> shared -> double atomics ----
    #pragma unroll
    for (int off = 16; off > 0; off >>= 1)
        #pragma unroll
        for (int k = 0; k < 27; k++)
            acc[k] += __shfl_down_sync(0xffffffffu, acc[k], off);

    __shared__ float sred[8][27];
    int lane = threadIdx.x & 31, wid = threadIdx.x >> 5;
    if (lane == 0)
        #pragma unroll
        for (int k = 0; k < 27; k++) sred[wid][k] = acc[k];
    __syncthreads();
    if (threadIdx.x < 27) {
        float sv = 0.f;
        #pragma unroll
        for (int w2 = 0; w2 < 8; w2++) sv += sred[w2][threadIdx.x];
        atomicAdd(&g_acc[b*27 + threadIdx.x], (double)sv);
    }

    // ---- last block performs the GN solve for all batches ----
    __shared__ bool amLast;
    __threadfence();
    if (threadIdx.x == 0) {
        unsigned int t = atomicAdd(&g_done, 1u);
        amLast = (t == (unsigned)(NBLK - 1));
        if (amLast) g_done = 0u;     // reset for the next launch
    }
    __syncthreads();
    if (amLast && threadIdx.x < BB) {
        __threadfence();
        solve_update(threadIdx.x, out);
    }
}

// ---------------- launch --------------------------------------------------------
extern "C" void kernel_launch(void* const* d_in, const int* in_sizes, int n_in,
                              void* d_out, int out_size) {
    const float* pose   = (const float*)d_in[0];
    const float* I0     = (const float*)d_in[1];
    const float* I1     = (const float*)d_in[2];
    const float* intr   = (const float*)d_in[5];
    const float* depth0 = (const float*)d_in[6];
    const float* depth1 = (const float*)d_in[7];

    prepK<<<(BB*NP + 255)/256, 256>>>(pose, intr, I0, depth0, depth1);

    for (int it = 0; it < 3; it++)
        iterK<<<NBLK, 256>>>(I1, intr, depth0, it == 2 ? (float*)d_out : nullptr);
}

// round 11
// speedup vs baseline: 1.1029x; 1.0543x over previous
#include <cuda_runtime.h>
#include <math.h>

#define BB 4
#define CC 8
#define HH 192
#define WW 256
#define NP (HH*WW)
#define GEOM_Wf 0.01f
#define NBLK (BB*(NP/256))      // 768 blocks, one 256-pixel chunk each

// ---------------- scratch (SoA planes; no allocation) -------------------------
__device__ float  g_V0[BB*3*NP];
__device__ float  g_N0[BB*3*NP];
__device__ float  g_dIx[BB*CC*NP];
__device__ float  g_dIy[BB*CC*NP];
__device__ float4 g_v1[BB*NP];
__device__ float  g_pose[BB*16];
__device__ double g_acc[BB*27];
__device__ unsigned int g_done = 0;

// ---------------- fused prep: vertices, normals, gradients, init --------------
__global__ void __launch_bounds__(256)
prepK(const float* __restrict__ pose, const float* __restrict__ intr,
      const float* __restrict__ I0,
      const float* __restrict__ depth0, const float* __restrict__ depth1) {
    int i = blockIdx.x*256 + threadIdx.x;
    if (blockIdx.x == 0) {
        int t = threadIdx.x;
        if (t < BB*16) g_pose[t] = pose[t];
        if (t < BB*27) g_acc[t]  = 0.0;
        if (t == 0)    g_done    = 0u;
    }
    if (i >= BB*NP) return;
    int b = i / NP, pix = i - b*NP;
    int h = pix / WW, w = pix - h*WW;
    int wm = max(w-1, 0), wp = min(w+1, WW-1);
    int hm = max(h-1, 0), hp = min(h+1, HH-1);

    float fx = intr[b*4+0], fy = intr[b*4+1], cx = intr[b*4+2], cy = intr[b*4+3];
    const float* D0 = depth0 + (size_t)b*NP;

    float px = ((float)w - cx) / fx;
    float py = ((float)h - cy) / fy;
    float d0 = D0[pix];
    float d1 = depth1[i];
    g_v1[i] = make_float4(px*d1, py*d1, d1, 0.f);

    g_V0[(b*3+0)*NP+pix] = px*d0;
    g_V0[(b*3+1)*NP+pix] = py*d0;
    g_V0[(b*3+2)*NP+pix] = d0;

    // V0 normal via analytic neighbor recompute (matches edge-pad central diff)
    float dxp = D0[h*WW+wp], dxm = D0[h*WW+wm];
    float dyp = D0[hp*WW+w], dym = D0[hm*WW+w];
    float pxp = ((float)wp - cx)/fx, pxm = ((float)wm - cx)/fx;
    float pyp = ((float)hp - cy)/fy, pym = ((float)hm - cy)/fy;
    float dx0 = (pxp*dxp - pxm*dxm) * 0.5f;
    float dx1 = (py*dxp  - py*dxm ) * 0.5f;
    float dx2 = (dxp     - dxm    ) * 0.5f;
    float dy0 = (px*dyp  - px*dym ) * 0.5f;
    float dy1 = (pyp*dyp - pym*dym) * 0.5f;
    float dy2 = (dyp     - dym    ) * 0.5f;
    float n0 = dx1*dy2 - dx2*dy1;
    float n1 = dx2*dy0 - dx0*dy2;
    float n2 = dx0*dy1 - dx1*dy0;
    float inv = 1.0f / sqrtf(n0*n0 + n1*n1 + n2*n2 + 1e-12f);
    g_N0[(b*3+0)*NP+pix] = n0*inv;
    g_N0[(b*3+1)*NP+pix] = n1*inv;
    g_N0[(b*3+2)*NP+pix] = n2*inv;

    #pragma unroll
    for (int c = 0; c < CC; c++) {
        const float* Ic = I0 + (size_t)(b*CC+c)*NP;
        g_dIx[(size_t)(b*CC+c)*NP+pix] = (Ic[h*WW+wp] - Ic[h*WW+wm]) * 0.5f;
        g_dIy[(size_t)(b*CC+c)*NP+pix] = (Ic[hp*WW+w] - Ic[hm*WW+w]) * 0.5f;
    }
}

// ---------------- helpers ------------------------------------------------------
__device__ __forceinline__ void bilin_setup(float uu, float vv, int* idx, float* wt) {
    float u0 = floorf(uu), v0 = floorf(vv);
    float du = uu - u0, dv = vv - v0;
    float us[2] = {u0, u0 + 1.0f};
    float vs[2] = {v0, v0 + 1.0f};
    float wu[2] = {1.0f - du, du};
    float wv[2] = {1.0f - dv, dv};
    #pragma unroll
    for (int j = 0; j < 2; j++)
        #pragma unroll
        for (int i2 = 0; i2 < 2; i2++) {
            float uf = us[i2], vf = vs[j];
            bool in = (uf >= 0.0f) && (uf <= (float)(WW-1)) &&
                      (vf >= 0.0f) && (vf <= (float)(HH-1));
            int ui = (int)fminf(fmaxf(uf, 0.0f), (float)(WW-1));
            int vi = (int)fminf(fmaxf(vf, 0.0f), (float)(HH-1));
            idx[j*2+i2] = vi*WW + ui;
            wt[j*2+i2]  = wu[i2]*wv[j] * (in ? 1.0f : 0.0f);
        }
}

// ---------------- per-batch GN solve + se3_exp + pose compose -----------------
__device__ __noinline__ void solve_update(int b, float* out) {
    double M[6][7];
    {
        int id = 0;
        double Hm[6][6];
        for (int i = 0; i < 6; i++)
            for (int j = i; j < 6; j++) {
                double vv = atomicAdd(&g_acc[b*27 + id], 0.0);   // L2-coherent read
                id++;
                Hm[i][j] = vv; Hm[j][i] = vv;
            }
        for (int i = 0; i < 6; i++) Hm[i][i] += 1e-6;
        for (int i = 0; i < 6; i++) {
            for (int j = 0; j < 6; j++) M[i][j] = Hm[i][j];
            M[i][6] = atomicAdd(&g_acc[b*27 + 21 + i], 0.0);
        }
    }
    for (int col = 0; col < 6; col++) {
        int piv = col; double mx = fabs(M[col][col]);
        for (int r = col+1; r < 6; r++)
            if (fabs(M[r][col]) > mx) { mx = fabs(M[r][col]); piv = r; }
        if (piv != col)
            for (int j = col; j < 7; j++) { double tmp = M[col][j]; M[col][j] = M[piv][j]; M[piv][j] = tmp; }
        double d = M[col][col];
        for (int r = col+1; r < 6; r++) {
            double f = M[r][col] / d;
            for (int j = col; j < 7; j++) M[r][j] -= f * M[col][j];
        }
    }
    double xi[6];
    for (int i = 5; i >= 0; i--) {
        double s = M[i][6];
        for (int j = i+1; j < 6; j++) s -= M[i][j]*xi[j];
        xi[i] = s / M[i][i];
    }

    double W0 = xi[0], W1 = xi[1], W2 = xi[2];
    double V0v = xi[3], V1vd = xi[4], V2v = xi[5];
    double th2 = W0*W0 + W1*W1 + W2*W2;
    bool small = th2 < 1e-8;
    double th2s = small ? 1.0 : th2;
    double th = sqrt(th2s);
    double Aa = small ? (1.0 - th2/6.0)       : (sin(th)/th);
    double Bc = small ? (0.5 - th2/24.0)      : ((1.0 - cos(th))/th2s);
    double Cc = small ? (1.0/6.0 - th2/120.0) : ((th - sin(th))/(th2s*th));
    double K[3][3] = {{0,-W2,W1},{W2,0,-W0},{-W1,W0,0}};
    double K2[3][3];
    for (int i = 0; i < 3; i++)
        for (int j = 0; j < 3; j++) {
            double s = 0.0;
            for (int k = 0; k < 3; k++) s += K[i][k]*K[k][j];
            K2[i][j] = s;
        }
    double Rm[3][3], Vm[3][3];
    for (int i = 0; i < 3; i++)
        for (int j = 0; j < 3; j++) {
            double eye = (i == j) ? 1.0 : 0.0;
            Rm[i][j] = eye + Aa*K[i][j] + Bc*K2[i][j];
            Vm[i][j] = eye + Bc*K[i][j] + Cc*K2[i][j];
        }
    double tt[3];
    tt[0] = Vm[0][0]*V0v + Vm[0][1]*V1vd + Vm[0][2]*V2v;
    tt[1] = Vm[1][0]*V0v + Vm[1][1]*V1vd + Vm[1][2]*V2v;
    tt[2] = Vm[2][0]*V0v + Vm[2][1]*V1vd + Vm[2][2]*V2v;

    double T[4][4] = {{Rm[0][0],Rm[0][1],Rm[0][2],tt[0]},
                      {Rm[1][0],Rm[1][1],Rm[1][2],tt[1]},
                      {Rm[2][0],Rm[2][1],Rm[2][2],tt[2]},
                      {0,0,0,1}};
    double Pold[4][4];
    for (int i = 0; i < 4; i++)
        for (int j = 0; j < 4; j++) Pold[i][j] = (double)g_pose[b*16 + i*4 + j];
    for (int i = 0; i < 4; i++)
        for (int j = 0; j < 4; j++) {
            double s = 0.0;
            for (int k = 0; k < 4; k++) s += T[i][k]*Pold[k][j];
            float fv = (float)s;
            g_pose[b*16 + i*4 + j] = fv;
            if (out) out[b*16 + i*4 + j] = fv;
        }
    for (int k = 0; k < 27; k++) g_acc[b*27 + k] = 0.0;
}

// ---------------- main per-iteration kernel (R3 body + last-block solve) ------
__global__ void __launch_bounds__(256, 3)
iterK(const float* __restrict__ I0, const float* __restrict__ I1,
      const float* __restrict__ intr, const float* __restrict__ depth0,
      float* __restrict__ out) {
    const int BPB = NP / 256;
    const int b   = blockIdx.x / BPB;
    const int pix = (blockIdx.x % BPB) * 256 + threadIdx.x;
    const size_t bNP = (size_t)b*NP;

    const float* P = g_pose + b*16;
    float R00=P[0], R01=P[1], R02=P[2],  t0=P[3];
    float R10=P[4], R11=P[5], R12=P[6],  t1=P[7];
    float R20=P[8], R21=P[9], R22=P[10], t2=P[11];
    float fx = intr[b*4+0], fy = intr[b*4+1], cx = intr[b*4+2], cy = intr[b*4+3];

    float4 V1v4 = g_v1[bNP + pix];
    float X1 = V1v4.x, Y1 = V1v4.y, Z1 = V1v4.z;
    float d1v = Z1;

    float x = R00*X1 + R01*Y1 + R02*Z1 + t0;
    float y = R10*X1 + R11*Y1 + R12*Z1 + t1;
    float z = R20*X1 + R21*Y1 + R22*Z1 + t2;

    bool  valid0 = z > 1e-8f;
    float zs = (fabsf(z) > 1e-8f) ? z : 1e-8f;
    float u = fx*x/zs + cx;
    float v = fy*y/zs + cy;
    bool inb = (u > 0.0f) && (u < (float)(WW-1)) && (v > 0.0f) && (v < (float)(HH-1));
    float d0 = depth0[bNP + pix];
    bool valid = inb && valid0 && (d0 > 0.0f) && (d1v > 0.0f);

    float Sxx=0.f, Sxy=0.f, Syy=0.f, Sxr=0.f, Syr=0.f;
    float Jg0=0.f, Jg1=0.f, Jg2=0.f, Jg3=0.f, Jg4=0.f, Jg5=0.f;
    float wgr=0.f, wg=0.f;

    // warp Jacobian rows (finite even when invalid; scalars are 0 then)
    float a  =  fx/zs;
    float bq = -fx*x/(zs*zs);
    float c2 =  fy/zs;
    float d2 = -fy*y/(zs*zs);
    float Jw0[6] = { bq*y,       a*z - bq*x, -a*y, a,   0.f, bq };
    float Jw1[6] = { -c2*z+d2*y, -d2*x,       c2*x, 0.f, c2,  d2 };

    if (valid) {
        // photometric sample coords: exact grid-clip round trip
        float gx = fminf(fmaxf((u/(float)(WW-1) - 0.5f)*2.0f, -2.0f), 2.0f);
        float gy = fminf(fmaxf((v/(float)(HH-1) - 0.5f)*2.0f, -2.0f), 2.0f);
        float up = (gx + 1.0f)*0.5f*(float)(WW-1);
        float vp = (gy + 1.0f)*0.5f*(float)(HH-1);
        int   idxp[4]; float wp_[4];
        bilin_setup(up, vp, idxp, wp_);

        #pragma unroll
        for (int c = 0; c < CC; c++) {
            const float* bI = I0    + (size_t)(b*CC+c)*NP;
            const float* bx = g_dIx + (size_t)(b*CC+c)*NP;
            const float* by = g_dIy + (size_t)(b*CC+c)*NP;
            float i0w = 0.f, gxv = 0.f, gyv = 0.f;
            #pragma unroll
            for (int k = 0; k < 4; k++) {
                i0w += wp_[k]*bI[idxp[k]];
                gxv += wp_[k]*bx[idxp[k]];
                gyv += wp_[k]*by[idxp[k]];
            }
            float r = I1[(size_t)(b*CC+c)*NP + pix] - i0w;
            float ar = fabsf(r);
            float wt = (ar <= 0.5f) ? 1.0f : 0.5f / fmaxf(ar, 1e-12f);
            float wgx = wt*gxv, wgy = wt*gyv;
            Sxx += wgx*gxv; Sxy += wgx*gyv; Syy += wgy*gyv;
            Sxr += wgx*r;   Syr += wgy*r;
        }

        // ---- geometric (ICP point-to-plane) row ----
        float ui = x/zs*fx + cx;
        float vi = y/zs*fy + cy;
        int   idxg[4]; float wg_[4];
        bilin_setup(ui, vi, idxg, wg_);

        float rv0=0.f, rv1=0.f, rv2=0.f, rn0=0.f, rn1=0.f, rn2=0.f;
        #pragma unroll
        for (int k = 0; k < 4; k++) {
            const float* bV = g_V0 + bNP*3 + idxg[k];
            const float* bN = g_N0 + bNP*3 + idxg[k];
            float wk = wg_[k];
            rv0 += wk*bV[0];    rv1 += wk*bV[NP];   rv2 += wk*bV[2*NP];
            rn0 += wk*bN[0];    rn1 += wk*bN[NP];   rn2 += wk*bN[2*NP];
        }
        float dx_ = x - rv0, dy_ = y - rv1, dz_ = z - rv2;
        float dn  = sqrtf(dx_*dx_ + dy_*dy_ + dz_*dz_ + 1e-12f);
        bool  occ = dn > 0.1f;

        float N0c = rn0*R00 + rn1*R10 + rn2*R20;
        float N1c = rn0*R01 + rn1*R11 + rn2*R21;
        float N2c = rn0*R02 + rn1*R12 + rn2*R22;
        float Jr0 = N1c*Z1 - N2c*Y1;
        float Jr1 = N2c*X1 - N0c*Z1;
        float Jr2 = N0c*Y1 - N1c*X1;

        float sdxy = d1v / 525.0f * 5.5f;
        float sdz  = d1v * d1v * 0.4f / (525.0f * 1.2f);
        float cov  = (N0c*N0c + N1c*N1c)*sdxy*sdxy + N2c*N2c*sdz*sdz;
        float sigma = sqrtf(cov + 1e-8f);
        float inv   = 1.0f / (sigma + 1e-8f);

        float res = (rn0*dx_ + rn1*dy_ + rn2*dz_) * inv;
        if (occ) res = 1e-6f;
        Jg0 = GEOM_Wf*(-Jr0*inv); Jg1 = GEOM_Wf*(-Jr1*inv); Jg2 = GEOM_Wf*(-Jr2*inv);
        Jg3 = GEOM_Wf*( N0c*inv); Jg4 = GEOM_Wf*( N1c*inv); Jg5 = GEOM_Wf*( N2c*inv);
        float rg = -GEOM_Wf*res;
        float arg = fabsf(rg);
        wg  = (arg <= 0.5f) ? 1.0f : 0.5f / fmaxf(arg, 1e-12f);
        wgr = wg * rg;
    }

    // ---- expansion: 27 = rank-2 photometric + rank-1 geometric ----
    float acc[27];
    {
        float Jga[6] = {Jg0, Jg1, Jg2, Jg3, Jg4, Jg5};
        float Pe[6], Qe[6];
        #pragma unroll
        for (int i2 = 0; i2 < 6; i2++) {
            Pe[i2] = Sxx*Jw0[i2] + Sxy*Jw1[i2];
            Qe[i2] = Sxy*Jw0[i2] + Syy*Jw1[i2];
        }
        int id = 0;
        #pragma unroll
        for (int i2 = 0; i2 < 6; i2++) {
            float wJg = wg * Jga[i2];
            #pragma unroll
            for (int j2 = i2; j2 < 6; j2++)
                acc[id++] = Pe[i2]*Jw0[j2] + Qe[i2]*Jw1[j2] + wJg*Jga[j2];
            acc[21+i2] = Sxr*Jw0[i2] + Syr*Jw1[i2] + wgr*Jga[i2];
        }
    }

    // ---- block reduction: warp shuffle -> shared -> double atomics ----
    #pragma unroll
    for (int off = 16; off > 0; off >>= 1)
        #pragma unroll
        for (int k = 0; k < 27; k++)
            acc[k] += __shfl_down_sync(0xffffffffu, acc[k], off);

    __shared__ float sred[8][27];
    int lane = threadIdx.x & 31, wid = threadIdx.x >> 5;
    if (lane == 0)
        #pragma unroll
        for (int k = 0; k < 27; k++) sred[wid][k] = acc[k];
    __syncthreads();
    if (threadIdx.x < 27) {
        float sv = 0.f;
        #pragma unroll
        for (int w2 = 0; w2 < 8; w2++) sv += sred[w2][threadIdx.x];
        atomicAdd(&g_acc[b*27 + threadIdx.x], (double)sv);
    }

    // ---- last block performs the GN solve for all batches ----
    __shared__ bool amLast;
    __threadfence();
    if (threadIdx.x == 0) {
        unsigned int t = atomicAdd(&g_done, 1u);
        amLast = (t == (unsigned)(NBLK - 1));
        if (amLast) g_done = 0u;     // reset for the next launch
    }
    __syncthreads();
    if (amLast && threadIdx.x < BB) {
        __threadfence();
        solve_update(threadIdx.x, out);
    }
}

// ---------------- launch --------------------------------------------------------
extern "C" void kernel_launch(void* const* d_in, const int* in_sizes, int n_in,
                              void* d_out, int out_size) {
    const float* pose   = (const float*)d_in[0];
    const float* I0     = (const float*)d_in[1];
    const float* I1     = (const float*)d_in[2];
    const float* intr   = (const float*)d_in[5];
    const float* depth0 = (const float*)d_in[6];
    const float* depth1 = (const float*)d_in[7];

    prepK<<<(BB*NP + 255)/256, 256>>>(pose, intr, I0, depth0, depth1);

    for (int it = 0; it < 3; it++)
        iterK<<<NBLK, 256>>>(I0, I1, intr, depth0, it == 2 ? (float*)d_out : nullptr);
}

// round 14
// speedup vs baseline: 1.7857x; 1.6191x over previous
#include <cuda_runtime.h>
#include <math.h>

#define BB 4
#define CC 8
#define HH 192
#define WW 256
#define NP (HH*WW)
#define GEOM_Wf 0.01f
#define NBLK (BB*(NP/256))      // 768 blocks, one 256-pixel chunk each

// ---------------- scratch (SoA planes; no allocation) -------------------------
__device__ float  g_V0[BB*3*NP];
__device__ float  g_N0[BB*3*NP];
__device__ float  g_dIx[BB*CC*NP];
__device__ float  g_dIy[BB*CC*NP];
__device__ float4 g_v1[BB*NP];
__device__ float  g_pose[BB*16];
__device__ double g_acc[BB*27];
__device__ unsigned int g_done = 0;

// ---------------- fused prep: vertices, normals, gradients, init --------------
__global__ void __launch_bounds__(256)
prepK(const float* __restrict__ pose, const float* __restrict__ intr,
      const float* __restrict__ I0,
      const float* __restrict__ depth0, const float* __restrict__ depth1) {
    int i = blockIdx.x*256 + threadIdx.x;
    if (blockIdx.x == 0) {
        int t = threadIdx.x;
        if (t < BB*16) g_pose[t] = pose[t];
        if (t < BB*27) g_acc[t]  = 0.0;
        if (t == 0)    g_done    = 0u;
    }
    if (i >= BB*NP) return;
    int b = i / NP, pix = i - b*NP;
    int h = pix / WW, w = pix - h*WW;
    int wm = max(w-1, 0), wp = min(w+1, WW-1);
    int hm = max(h-1, 0), hp = min(h+1, HH-1);

    float fx = intr[b*4+0], fy = intr[b*4+1], cx = intr[b*4+2], cy = intr[b*4+3];
    const float* D0 = depth0 + (size_t)b*NP;

    float px = ((float)w - cx) / fx;
    float py = ((float)h - cy) / fy;
    float d0 = D0[pix];
    float d1 = depth1[i];
    g_v1[i] = make_float4(px*d1, py*d1, d1, 0.f);

    g_V0[(b*3+0)*NP+pix] = px*d0;
    g_V0[(b*3+1)*NP+pix] = py*d0;
    g_V0[(b*3+2)*NP+pix] = d0;

    // V0 normal via analytic neighbor recompute (matches edge-pad central diff)
    float dxp = D0[h*WW+wp], dxm = D0[h*WW+wm];
    float dyp = D0[hp*WW+w], dym = D0[hm*WW+w];
    float pxp = ((float)wp - cx)/fx, pxm = ((float)wm - cx)/fx;
    float pyp = ((float)hp - cy)/fy, pym = ((float)hm - cy)/fy;
    float dx0 = (pxp*dxp - pxm*dxm) * 0.5f;
    float dx1 = (py*dxp  - py*dxm ) * 0.5f;
    float dx2 = (dxp     - dxm    ) * 0.5f;
    float dy0 = (px*dyp  - px*dym ) * 0.5f;
    float dy1 = (pyp*dyp - pym*dym) * 0.5f;
    float dy2 = (dyp     - dym    ) * 0.5f;
    float n0 = dx1*dy2 - dx2*dy1;
    float n1 = dx2*dy0 - dx0*dy2;
    float n2 = dx0*dy1 - dx1*dy0;
    float inv = 1.0f / sqrtf(n0*n0 + n1*n1 + n2*n2 + 1e-12f);
    g_N0[(b*3+0)*NP+pix] = n0*inv;
    g_N0[(b*3+1)*NP+pix] = n1*inv;
    g_N0[(b*3+2)*NP+pix] = n2*inv;

    #pragma unroll
    for (int c = 0; c < CC; c++) {
        const float* Ic = I0 + (size_t)(b*CC+c)*NP;
        g_dIx[(size_t)(b*CC+c)*NP+pix] = (Ic[h*WW+wp] - Ic[h*WW+wm]) * 0.5f;
        g_dIy[(size_t)(b*CC+c)*NP+pix] = (Ic[hp*WW+w] - Ic[hm*WW+w]) * 0.5f;
    }
}

// ---------------- helpers ------------------------------------------------------
__device__ __forceinline__ void bilin_setup(float uu, float vv, int* idx, float* wt) {
    float u0 = floorf(uu), v0 = floorf(vv);
    float du = uu - u0, dv = vv - v0;
    float us[2] = {u0, u0 + 1.0f};
    float vs[2] = {v0, v0 + 1.0f};
    float wu[2] = {1.0f - du, du};
    float wv[2] = {1.0f - dv, dv};
    #pragma unroll
    for (int j = 0; j < 2; j++)
        #pragma unroll
        for (int i2 = 0; i2 < 2; i2++) {
            float uf = us[i2], vf = vs[j];
            bool in = (uf >= 0.0f) && (uf <= (float)(WW-1)) &&
                      (vf >= 0.0f) && (vf <= (float)(HH-1));
            int ui = (int)fminf(fmaxf(uf, 0.0f), (float)(WW-1));
            int vi = (int)fminf(fmaxf(vf, 0.0f), (float)(HH-1));
            idx[j*2+i2] = vi*WW + ui;
            wt[j*2+i2]  = wu[i2]*wv[j] * (in ? 1.0f : 0.0f);
        }
}

// ---------------- per-batch GN solve + se3_exp + pose compose (float32) -------
__device__ __noinline__ void solve_update(int b, float* out) {
    float M[6][7];
    {
        int id = 0;
        float Hm[6][6];
        for (int i = 0; i < 6; i++)
            for (int j = i; j < 6; j++) {
                float vv = (float)atomicAdd(&g_acc[b*27 + id], 0.0);  // L2-coherent read
                id++;
                Hm[i][j] = vv; Hm[j][i] = vv;
            }
        for (int i = 0; i < 6; i++) Hm[i][i] += 1e-6f;
        for (int i = 0; i < 6; i++) {
            for (int j = 0; j < 6; j++) M[i][j] = Hm[i][j];
            M[i][6] = (float)atomicAdd(&g_acc[b*27 + 21 + i], 0.0);
        }
    }
    for (int col = 0; col < 6; col++) {
        int piv = col; float mx = fabsf(M[col][col]);
        for (int r = col+1; r < 6; r++)
            if (fabsf(M[r][col]) > mx) { mx = fabsf(M[r][col]); piv = r; }
        if (piv != col)
            for (int j = col; j < 7; j++) { float tmp = M[col][j]; M[col][j] = M[piv][j]; M[piv][j] = tmp; }
        float d = M[col][col];
        for (int r = col+1; r < 6; r++) {
            float f = M[r][col] / d;
            for (int j = col; j < 7; j++) M[r][j] -= f * M[col][j];
        }
    }
    float xi[6];
    for (int i = 5; i >= 0; i--) {
        float s = M[i][6];
        for (int j = i+1; j < 6; j++) s -= M[i][j]*xi[j];
        xi[i] = s / M[i][i];
    }

    // se3_exp (float, matches reference float32 path)
    float W0 = xi[0], W1 = xi[1], W2 = xi[2];
    float V0v = xi[3], V1vd = xi[4], V2v = xi[5];
    float th2 = W0*W0 + W1*W1 + W2*W2;
    bool small = th2 < 1e-8f;
    float th2s = small ? 1.0f : th2;
    float th = sqrtf(th2s);
    float Aa = small ? (1.0f - th2/6.0f)        : (sinf(th)/th);
    float Bc = small ? (0.5f - th2/24.0f)       : ((1.0f - cosf(th))/th2s);
    float Cc = small ? (1.0f/6.0f - th2/120.0f) : ((th - sinf(th))/(th2s*th));
    float K[3][3] = {{0,-W2,W1},{W2,0,-W0},{-W1,W0,0}};
    float K2[3][3];
    for (int i = 0; i < 3; i++)
        for (int j = 0; j < 3; j++) {
            float s = 0.f;
            for (int k = 0; k < 3; k++) s += K[i][k]*K[k][j];
            K2[i][j] = s;
        }
    float Rm[3][3], Vm[3][3];
    for (int i = 0; i < 3; i++)
        for (int j = 0; j < 3; j++) {
            float eye = (i == j) ? 1.0f : 0.0f;
            Rm[i][j] = eye + Aa*K[i][j] + Bc*K2[i][j];
            Vm[i][j] = eye + Bc*K[i][j] + Cc*K2[i][j];
        }
    float tt[3];
    tt[0] = Vm[0][0]*V0v + Vm[0][1]*V1vd + Vm[0][2]*V2v;
    tt[1] = Vm[1][0]*V0v + Vm[1][1]*V1vd + Vm[1][2]*V2v;
    tt[2] = Vm[2][0]*V0v + Vm[2][1]*V1vd + Vm[2][2]*V2v;

    float T[4][4] = {{Rm[0][0],Rm[0][1],Rm[0][2],tt[0]},
                     {Rm[1][0],Rm[1][1],Rm[1][2],tt[1]},
                     {Rm[2][0],Rm[2][1],Rm[2][2],tt[2]},
                     {0,0,0,1}};
    float Pold[4][4];
    for (int i = 0; i < 4; i++)
        for (int j = 0; j < 4; j++) Pold[i][j] = g_pose[b*16 + i*4 + j];
    for (int i = 0; i < 4; i++)
        for (int j = 0; j < 4; j++) {
            float s = 0.f;
            for (int k = 0; k < 4; k++) s += T[i][k]*Pold[k][j];
            g_pose[b*16 + i*4 + j] = s;
            if (out) out[b*16 + i*4 + j] = s;
        }
    for (int k = 0; k < 27; k++) g_acc[b*27 + k] = 0.0;
}

// ---------------- main per-iteration kernel (R3 body + last-block solve) ------
__global__ void __launch_bounds__(256, 3)
iterK(const float* __restrict__ I0, const float* __restrict__ I1,
      const float* __restrict__ intr, const float* __restrict__ depth0,
      float* __restrict__ out) {
    const int BPB = NP / 256;
    const int b   = blockIdx.x / BPB;
    const int pix = (blockIdx.x % BPB) * 256 + threadIdx.x;
    const size_t bNP = (size_t)b*NP;

    const float* P = g_pose + b*16;
    float R00=P[0], R01=P[1], R02=P[2],  t0=P[3];
    float R10=P[4], R11=P[5], R12=P[6],  t1=P[7];
    float R20=P[8], R21=P[9], R22=P[10], t2=P[11];
    float fx = intr[b*4+0], fy = intr[b*4+1], cx = intr[b*4+2], cy = intr[b*4+3];

    float4 V1v4 = g_v1[bNP + pix];
    float X1 = V1v4.x, Y1 = V1v4.y, Z1 = V1v4.z;
    float d1v = Z1;

    float x = R00*X1 + R01*Y1 + R02*Z1 + t0;
    float y = R10*X1 + R11*Y1 + R12*Z1 + t1;
    float z = R20*X1 + R21*Y1 + R22*Z1 + t2;

    bool  valid0 = z > 1e-8f;
    float zs = (fabsf(z) > 1e-8f) ? z : 1e-8f;
    float u = fx*x/zs + cx;
    float v = fy*y/zs + cy;
    bool inb = (u > 0.0f) && (u < (float)(WW-1)) && (v > 0.0f) && (v < (float)(HH-1));
    float d0 = depth0[bNP + pix];
    bool valid = inb && valid0 && (d0 > 0.0f) && (d1v > 0.0f);

    float Sxx=0.f, Sxy=0.f, Syy=0.f, Sxr=0.f, Syr=0.f;
    float Jg0=0.f, Jg1=0.f, Jg2=0.f, Jg3=0.f, Jg4=0.f, Jg5=0.f;
    float wgr=0.f, wg=0.f;

    // warp Jacobian rows (finite even when invalid; scalars are 0 then)
    float a  =  fx/zs;
    float bq = -fx*x/(zs*zs);
    float c2 =  fy/zs;
    float d2 = -fy*y/(zs*zs);
    float Jw0[6] = { bq*y,       a*z - bq*x, -a*y, a,   0.f, bq };
    float Jw1[6] = { -c2*z+d2*y, -d2*x,       c2*x, 0.f, c2,  d2 };

    if (valid) {
        // photometric sample coords: exact grid-clip round trip
        float gx = fminf(fmaxf((u/(float)(WW-1) - 0.5f)*2.0f, -2.0f), 2.0f);
        float gy = fminf(fmaxf((v/(float)(HH-1) - 0.5f)*2.0f, -2.0f), 2.0f);
        float up = (gx + 1.0f)*0.5f*(float)(WW-1);
        float vp = (gy + 1.0f)*0.5f*(float)(HH-1);
        int   idxp[4]; float wp_[4];
        bilin_setup(up, vp, idxp, wp_);

        #pragma unroll
        for (int c = 0; c < CC; c++) {
            const float* bI = I0    + (size_t)(b*CC+c)*NP;
            const float* bx = g_dIx + (size_t)(b*CC+c)*NP;
            const float* by = g_dIy + (size_t)(b*CC+c)*NP;
            float i0w = 0.f, gxv = 0.f, gyv = 0.f;
            #pragma unroll
            for (int k = 0; k < 4; k++) {
                i0w += wp_[k]*bI[idxp[k]];
                gxv += wp_[k]*bx[idxp[k]];
                gyv += wp_[k]*by[idxp[k]];
            }
            float r = I1[(size_t)(b*CC+c)*NP + pix] - i0w;
            float ar = fabsf(r);
            float wt = (ar <= 0.5f) ? 1.0f : 0.5f / fmaxf(ar, 1e-12f);
            float wgx = wt*gxv, wgy = wt*gyv;
            Sxx += wgx*gxv; Sxy += wgx*gyv; Syy += wgy*gyv;
            Sxr += wgx*r;   Syr += wgy*r;
        }

        // ---- geometric (ICP point-to-plane) row ----
        float ui = x/zs*fx + cx;
        float vi = y/zs*fy + cy;
        int   idxg[4]; float wg_[4];
        bilin_setup(ui, vi, idxg, wg_);

        float rv0=0.f, rv1=0.f, rv2=0.f, rn0=0.f, rn1=0.f, rn2=0.f;
        #pragma unroll
        for (int k = 0; k < 4; k++) {
            const float* bV = g_V0 + bNP*3 + idxg[k];
            const float* bN = g_N0 + bNP*3 + idxg[k];
            float wk = wg_[k];
            rv0 += wk*bV[0];    rv1 += wk*bV[NP];   rv2 += wk*bV[2*NP];
            rn0 += wk*bN[0];    rn1 += wk*bN[NP];   rn2 += wk*bN[2*NP];
        }
        float dx_ = x - rv0, dy_ = y - rv1, dz_ = z - rv2;
        float dn  = sqrtf(dx_*dx_ + dy_*dy_ + dz_*dz_ + 1e-12f);
        bool  occ = dn > 0.1f;

        float N0c = rn0*R00 + rn1*R10 + rn2*R20;
        float N1c = rn0*R01 + rn1*R11 + rn2*R21;
        float N2c = rn0*R02 + rn1*R12 + rn2*R22;
        float Jr0 = N1c*Z1 - N2c*Y1;
        float Jr1 = N2c*X1 - N0c*Z1;
        float Jr2 = N0c*Y1 - N1c*X1;

        float sdxy = d1v / 525.0f * 5.5f;
        float sdz  = d1v * d1v * 0.4f / (525.0f * 1.2f);
        float cov  = (N0c*N0c + N1c*N1c)*sdxy*sdxy + N2c*N2c*sdz*sdz;
        float sigma = sqrtf(cov + 1e-8f);
        float inv   = 1.0f / (sigma + 1e-8f);

        float res = (rn0*dx_ + rn1*dy_ + rn2*dz_) * inv;
        if (occ) res = 1e-6f;
        Jg0 = GEOM_Wf*(-Jr0*inv); Jg1 = GEOM_Wf*(-Jr1*inv); Jg2 = GEOM_Wf*(-Jr2*inv);
        Jg3 = GEOM_Wf*( N0c*inv); Jg4 = GEOM_Wf*( N1c*inv); Jg5 = GEOM_Wf*( N2c*inv);
        float rg = -GEOM_Wf*res;
        float arg = fabsf(rg);
        wg  = (arg <= 0.5f) ? 1.0f : 0.5f / fmaxf(arg, 1e-12f);
        wgr = wg * rg;
    }

    // ---- expansion: 27 = rank-2 photometric + rank-1 geometric ----
    float acc[27];
    {
        float Jga[6] = {Jg0, Jg1, Jg2, Jg3, Jg4, Jg5};
        float Pe[6], Qe[6];
        #pragma unroll
        for (int i2 = 0; i2 < 6; i2++) {
            Pe[i2] = Sxx*Jw0[i2] + Sxy*Jw1[i2];
            Qe[i2] = Sxy*Jw0[i2] + Syy*Jw1[i2];
        }
        int id = 0;
        #pragma unroll
        for (int i2 = 0; i2 < 6; i2++) {
            float wJg = wg * Jga[i2];
            #pragma unroll
            for (int j2 = i2; j2 < 6; j2++)
                acc[id++] = Pe[i2]*Jw0[j2] + Qe[i2]*Jw1[j2] + wJg*Jga[j2];
            acc[21+i2] = Sxr*Jw0[i2] + Syr*Jw1[i2] + wgr*Jga[i2];
        }
    }

    // ---- block reduction: warp shuffle -> shared -> double atomics ----
    #pragma unroll
    for (int off = 16; off > 0; off >>= 1)
        #pragma unroll
        for (int k = 0; k < 27; k++)
            acc[k] += __shfl_down_sync(0xffffffffu, acc[k], off);

    __shared__ float sred[8][27];
    int lane = threadIdx.x & 31, wid = threadIdx.x >> 5;
    if (lane == 0)
        #pragma unroll
        for (int k = 0; k < 27; k++) sred[wid][k] = acc[k];
    __syncthreads();
    if (threadIdx.x < 27) {
        float sv = 0.f;
        #pragma unroll
        for (int w2 = 0; w2 < 8; w2++) sv += sred[w2][threadIdx.x];
        atomicAdd(&g_acc[b*27 + threadIdx.x], (double)sv);
    }

    // ---- last block performs the GN solve for all batches ----
    __shared__ bool amLast;
    __threadfence();
    if (threadIdx.x == 0) {
        unsigned int t = atomicAdd(&g_done, 1u);
        amLast = (t == (unsigned)(NBLK - 1));
        if (amLast) g_done = 0u;     // reset for the next launch
    }
    __syncthreads();
    if (amLast && threadIdx.x < BB) {
        __threadfence();
        solve_update(threadIdx.x, out);
    }
}

// ---------------- launch --------------------------------------------------------
extern "C" void kernel_launch(void* const* d_in, const int* in_sizes, int n_in,
                              void* d_out, int out_size) {
    const float* pose   = (const float*)d_in[0];
    const float* I0     = (const float*)d_in[1];
    const float* I1     = (const float*)d_in[2];
    const float* intr   = (const float*)d_in[5];
    const float* depth0 = (const float*)d_in[6];
    const float* depth1 = (const float*)d_in[7];

    prepK<<<(BB*NP + 255)/256, 256>>>(pose, intr, I0, depth0, depth1);

    for (int it = 0; it < 3; it++)
        iterK<<<NBLK, 256>>>(I0, I1, intr, depth0, it == 2 ? (float*)d_out : nullptr);
}